// round 5
// baseline (speedup 1.0000x reference)
#include <cuda_runtime.h>
#include <cstdint>

// ---------------------------------------------------------------------------
// RSSM observe scan, GB300 — round 4.
//   k_rssm v3: 64 CTAs x 8 rows, 640 threads, dynamic smem (~111KB).
//   All matmul phases: LDG.128 weight loads feeding fma.rn.f32x2 directly
//   (accumulators pack column-pairs), duplicated activations in smem,
//   K-split segments + smem partial reduction.
// ---------------------------------------------------------------------------

#define Bc 512
#define Tc 64
#define Ec 1024
#define Ac 32
#define Sc 30
#define Dc 200
#define Hc 200
#define SSc 230
#define OUTC 380
#define Rr 8
#define NCTA (Bc / Rr)   // 64

typedef unsigned long long ull;

__device__ float g_pre_inp[Tc * Bc * Hc];
__device__ float g_pre_obs[Tc * Bc * Hc];

// ---- packed f32x2 helpers -------------------------------------------------
__device__ __forceinline__ ull pk2(float a, float b) {
    ull r; asm("mov.b64 %0, {%1, %2};" : "=l"(r) : "f"(a), "f"(b)); return r;
}
__device__ __forceinline__ ull dup2(float a) {
    ull r; asm("mov.b64 %0, {%1, %1};" : "=l"(r) : "f"(a)); return r;
}
__device__ __forceinline__ float2 up2(ull v) {
    float x, y; asm("mov.b64 {%0, %1}, %2;" : "=f"(x), "=f"(y) : "l"(v));
    return make_float2(x, y);
}
__device__ __forceinline__ void fma2(ull& acc, ull a, ull b) {
    asm("fma.rn.f32x2 %0, %1, %2, %0;" : "+l"(acc) : "l"(a), "l"(b));
}

__device__ __forceinline__ float sigm(float x) { return 1.0f / (1.0f + __expf(-x)); }
__device__ __forceinline__ float eluf(float x) { return x > 0.0f ? x : expm1f(x); }
__device__ __forceinline__ float softplusf(float x) {
    return x > 15.0f ? x : log1pf(__expf(x));
}

// ===========================================================================
// k_pre_obs: [32768, 1024] x [1024, 200]  (weight rows 200..1223 of w_obs_out)
// (minor change vs r3: As padded to 72 so inner reads are 4x LDS.128)
// ===========================================================================
__global__ void __launch_bounds__(128) k_pre_obs(const float* __restrict__ embed,
                                                 const float* __restrict__ w_obs,
                                                 const float* __restrict__ b_obs) {
    __shared__ __align__(16) float As[16][72];
    const int tid = threadIdx.x;
    const int jp = tid & 31, rg = tid >> 5;
    const int row0 = blockIdx.x * 64;
    const int j0 = blockIdx.y * 64 + jp * 2;
    const bool act = (j0 < Hc);
    const int rbase = rg * 16;

    ull acc[16];
#pragma unroll
    for (int i = 0; i < 16; i++) acc[i] = 0ull;

    for (int k0 = 0; k0 < Ec; k0 += 16) {
#pragma unroll
        for (int i = 0; i < 8; i++) {
            int lin = tid + i * 128;
            int kk = lin & 15, r = lin >> 4;
            int rowg = row0 + r;
            int tt = rowg >> 9, bb = rowg & 511;
            As[kk][r] = embed[(size_t)(bb * Tc + tt) * Ec + k0 + kk];
        }
        __syncthreads();
        if (act) {
#pragma unroll
            for (int kk = 0; kk < 16; kk++) {
                float2 w = *reinterpret_cast<const float2*>(
                    w_obs + (size_t)(Dc + k0 + kk) * Hc + j0);
                ull wx = dup2(w.x), wy = dup2(w.y);
                const ulonglong2* ap2 =
                    reinterpret_cast<const ulonglong2*>(&As[kk][rbase]);
#pragma unroll
                for (int q = 0; q < 4; q++) {
                    ulonglong2 av = ap2[q];
                    fma2(acc[4 * q + 0], av.x, wx);
                    fma2(acc[4 * q + 1], av.x, wy);
                    fma2(acc[4 * q + 2], av.y, wx);
                    fma2(acc[4 * q + 3], av.y, wy);
                }
            }
        }
        __syncthreads();
    }
    if (act) {
        float bx = b_obs[j0], by = b_obs[j0 + 1];
#pragma unroll
        for (int p = 0; p < 8; p++) {
            float2 va = up2(acc[2 * p]), vb = up2(acc[2 * p + 1]);
            int r = row0 + rbase + 2 * p;
            *reinterpret_cast<float2*>(g_pre_obs + (size_t)r * Hc + j0) =
                make_float2(va.x + bx, vb.x + by);
            *reinterpret_cast<float2*>(g_pre_obs + (size_t)(r + 1) * Hc + j0) =
                make_float2(va.y + bx, vb.y + by);
        }
    }
}

// ===========================================================================
// k_pre_inp: [32768, 262] x [262, 200]
// ===========================================================================
__global__ void __launch_bounds__(128) k_pre_inp(const float* __restrict__ ctx,
                                                 const float* __restrict__ actn,
                                                 const float* __restrict__ w_inp,
                                                 const float* __restrict__ b_inp) {
    __shared__ __align__(16) float As[16][72];
    const int tid = threadIdx.x;
    const int jp = tid & 31, rg = tid >> 5;
    const int row0 = blockIdx.x * 64;
    const int j0 = blockIdx.y * 64 + jp * 2;
    const bool act = (j0 < Hc);
    const int rbase = rg * 16;

    ull acc[16];
#pragma unroll
    for (int i = 0; i < 16; i++) acc[i] = 0ull;

    for (int k0 = 0; k0 < 272; k0 += 16) {
#pragma unroll
        for (int i = 0; i < 8; i++) {
            int lin = tid + i * 128;
            int kk = lin & 15, r = lin >> 4;
            int rowg = row0 + r;
            int tt = rowg >> 9, bb = rowg & 511;
            int k = k0 + kk;
            float v = 0.0f;
            if (k < SSc)            v = ctx[(size_t)(bb * Tc + tt) * SSc + k];
            else if (k < SSc + Ac)  v = actn[(size_t)(bb * Tc + tt) * Ac + (k - SSc)];
            As[kk][r] = v;
        }
        __syncthreads();
        if (act) {
#pragma unroll
            for (int kk = 0; kk < 16; kk++) {
                int kw = (k0 + kk < SSc + Ac) ? (k0 + kk) : (SSc + Ac - 1);
                float2 w = *reinterpret_cast<const float2*>(
                    w_inp + (size_t)(Sc + kw) * Hc + j0);
                ull wx = dup2(w.x), wy = dup2(w.y);
                const ulonglong2* ap2 =
                    reinterpret_cast<const ulonglong2*>(&As[kk][rbase]);
#pragma unroll
                for (int q = 0; q < 4; q++) {
                    ulonglong2 av = ap2[q];
                    fma2(acc[4 * q + 0], av.x, wx);
                    fma2(acc[4 * q + 1], av.x, wy);
                    fma2(acc[4 * q + 2], av.y, wx);
                    fma2(acc[4 * q + 3], av.y, wy);
                }
            }
        }
        __syncthreads();
    }
    if (act) {
        float bx = b_inp[j0], by = b_inp[j0 + 1];
#pragma unroll
        for (int p = 0; p < 8; p++) {
            float2 va = up2(acc[2 * p]), vb = up2(acc[2 * p + 1]);
            int r = row0 + rbase + 2 * p;
            *reinterpret_cast<float2*>(g_pre_inp + (size_t)r * Hc + j0) =
                make_float2(va.x + bx, vb.x + by);
            *reinterpret_cast<float2*>(g_pre_inp + (size_t)(r + 1) * Hc + j0) =
                make_float2(va.y + bx, vb.y + by);
        }
    }
}

// ===========================================================================
// k_rssm v3 — dynamic smem layout (bytes):
//  xd_dup   [400][8] ull   @      0   (25600)  x||d, value duplicated (a,a)
//  dn_dup   [200][8] ull   @  25600   (12800)  deter_new duplicated
//  part     [9600]  float  @  38400   (38400)  K-segment partials (reused)
//  hho_dup  [400][8] ull   @  76800   (25600)  h||ho duplicated
//  stS      [8][64] float  @ 102400   ( 2048)
//  soS      [8][64] float  @ 104448   ( 2048)
//  st_f     [32][8] float  @ 106496   ( 1024)  stoch plain
//  bgru[600]               @ 107520   ( 2400)
//  bimg[200]               @ 109920   (  800)
//  bims[64]                @ 110720   (  256)
//  bobs[64]                @ 110976   (  256)   total 111232
// ===========================================================================
#define SMEM_BYTES 111232

__global__ void __launch_bounds__(640, 1) k_rssm(
    const float* __restrict__ noise_p, const float* __restrict__ noise_o,
    const float* __restrict__ w_inp,  const float* __restrict__ w_gru,
    const float* __restrict__ b_gru_g,
    const float* __restrict__ w_img,  const float* __restrict__ b_img_g,
    const float* __restrict__ w_obsd,
    const float* __restrict__ w_ims,  const float* __restrict__ b_ims_g,
    const float* __restrict__ w_obst, const float* __restrict__ b_obst_g,
    float* __restrict__ out) {
    extern __shared__ __align__(16) char smem_raw[];
    ull*   xd_dup  = reinterpret_cast<ull*>(smem_raw);
    ull*   dn_dup  = reinterpret_cast<ull*>(smem_raw + 25600);
    float* part    = reinterpret_cast<float*>(smem_raw + 38400);
    ull*   hho_dup = reinterpret_cast<ull*>(smem_raw + 76800);
    float* stS     = reinterpret_cast<float*>(smem_raw + 102400);
    float* soS     = reinterpret_cast<float*>(smem_raw + 104448);
    float* st_f    = reinterpret_cast<float*>(smem_raw + 106496);
    float* bgru    = reinterpret_cast<float*>(smem_raw + 107520);
    float* bimg    = reinterpret_cast<float*>(smem_raw + 109920);
    float* bims    = reinterpret_cast<float*>(smem_raw + 110720);
    float* bobs    = reinterpret_cast<float*>(smem_raw + 110976);

    const int tid = threadIdx.x;
    const int b0 = blockIdx.x * Rr;
    const float* xd_fd = reinterpret_cast<const float*>(xd_dup);
    const float* dn_fd = reinterpret_cast<const float*>(dn_dup);

    for (int i = tid; i < 600; i += 640) bgru[i] = b_gru_g[i];
    for (int i = tid; i < Hc; i += 640) bimg[i] = b_img_g[i];
    if (tid < 60) { bims[tid] = b_ims_g[tid]; bobs[tid] = b_obst_g[tid]; }
    for (int i = tid; i < 200 * 8; i += 640) xd_dup[200 * 8 + i] = 0ull;  // d=0
    for (int i = tid; i < 32 * 8; i += 640) st_f[i] = 0.0f;               // s=0
    __syncthreads();

    for (int t = 0; t < Tc; t++) {
        // ---- phase 1: x = elu(stoch @ Wis + pre_inp[t]); write dup ----
        if (tid < 400) {
            const int j = tid >> 1, rh = tid & 1;
            const float* pi = g_pre_inp + ((size_t)t * Bc + b0) * Hc + j;
            float a0 = pi[(rh * 4 + 0) * Hc], a1 = pi[(rh * 4 + 1) * Hc];
            float a2 = pi[(rh * 4 + 2) * Hc], a3 = pi[(rh * 4 + 3) * Hc];
#pragma unroll
            for (int k = 0; k < Sc; k++) {
                float w = w_inp[k * Hc + j];
                float4 s = *reinterpret_cast<const float4*>(&st_f[k * 8 + rh * 4]);
                a0 = fmaf(w, s.x, a0); a1 = fmaf(w, s.y, a1);
                a2 = fmaf(w, s.z, a2); a3 = fmaf(w, s.w, a3);
            }
            ull* xo = &xd_dup[j * 8 + rh * 4];
            xo[0] = dup2(eluf(a0)); xo[1] = dup2(eluf(a1));
            xo[2] = dup2(eluf(a2)); xo[3] = dup2(eluf(a3));
        }
        __syncthreads();

        // ---- phase 2: GRU preacts [400x600], col-pair accs, k-split 2 ----
        if (tid < 600) {
            const int cg = tid % 150;          // 4-col group
            const int z = tid / 150;
            const int rh = z & 1, seg = z >> 1;
            const ulonglong2* Wp = reinterpret_cast<const ulonglong2*>(w_gru) +
                                   (size_t)seg * 200 * 150 + cg;
            const ulonglong2* Ap = reinterpret_cast<const ulonglong2*>(xd_dup) +
                                   (seg * 200) * 4 + rh * 2;
            ull A0 = 0, A1 = 0, A2 = 0, A3 = 0, A4 = 0, A5 = 0, A6 = 0, A7 = 0;
#pragma unroll 4
            for (int k = 0; k < 200; k++) {
                ulonglong2 w = Wp[(size_t)k * 150];
                ulonglong2 a01 = Ap[k * 4];
                ulonglong2 a23 = Ap[k * 4 + 1];
                fma2(A0, w.x, a01.x); fma2(A1, w.y, a01.x);
                fma2(A2, w.x, a01.y); fma2(A3, w.y, a01.y);
                fma2(A4, w.x, a23.x); fma2(A5, w.y, a23.x);
                fma2(A6, w.x, a23.y); fma2(A7, w.y, a23.y);
            }
            float* P = part + (seg * 600 + cg * 4) * 8 + rh * 4;
            float2 v;
            v = up2(A0); P[0 * 8 + 0] = v.x; P[1 * 8 + 0] = v.y;
            v = up2(A1); P[2 * 8 + 0] = v.x; P[3 * 8 + 0] = v.y;
            v = up2(A2); P[0 * 8 + 1] = v.x; P[1 * 8 + 1] = v.y;
            v = up2(A3); P[2 * 8 + 1] = v.x; P[3 * 8 + 1] = v.y;
            v = up2(A4); P[0 * 8 + 2] = v.x; P[1 * 8 + 2] = v.y;
            v = up2(A5); P[2 * 8 + 2] = v.x; P[3 * 8 + 2] = v.y;
            v = up2(A6); P[0 * 8 + 3] = v.x; P[1 * 8 + 3] = v.y;
            v = up2(A7); P[2 * 8 + 3] = v.x; P[3 * 8 + 3] = v.y;
        }
        __syncthreads();

        // ---- combine GRU: gates -> deter_new (dup) ----
        if (tid < 400) {
            const int j = tid >> 1, rh = tid & 1;
            const float bR = bgru[j], bC = bgru[200 + j], bU = bgru[400 + j];
#pragma unroll
            for (int r = 0; r < 4; r++) {
                const int rr = rh * 4 + r;
                float R = bR + part[j * 8 + rr] + part[(600 + j) * 8 + rr];
                float C = bC + part[(200 + j) * 8 + rr] + part[(800 + j) * 8 + rr];
                float U = bU + part[(400 + j) * 8 + rr] + part[(1000 + j) * 8 + rr]
                          - 1.0f;
                float reset = sigm(R);
                float cand  = tanhf(reset * C);
                float upd   = sigm(U);
                float dprev = xd_fd[((200 + j) * 8 + rr) * 2];
                float dnv = upd * cand + (1.0f - upd) * dprev;
                dn_dup[j * 8 + rr] = dup2(dnv);
            }
        }
        __syncthreads();

        // ---- phase 3: h = dn@Wimg, ho = dn@Wobsd ; k-split 2 ----
        if (tid < 400) {
            const int cg = tid % 100;          // 4-col group over 400 cols
            const int z = tid / 100;
            const int rh = z & 1, seg = z >> 1;
            const float* W = (cg < 50)
                ? (w_img + (size_t)seg * 100 * 200 + cg * 4)
                : (w_obsd + (size_t)seg * 100 * 200 + (cg - 50) * 4);
            const ulonglong2* Wp = reinterpret_cast<const ulonglong2*>(W);
            const ulonglong2* Ap = reinterpret_cast<const ulonglong2*>(dn_dup) +
                                   (seg * 100) * 4 + rh * 2;
            ull A0 = 0, A1 = 0, A2 = 0, A3 = 0, A4 = 0, A5 = 0, A6 = 0, A7 = 0;
#pragma unroll 4
            for (int k = 0; k < 100; k++) {
                ulonglong2 w = Wp[(size_t)k * 50];
                ulonglong2 a01 = Ap[k * 4];
                ulonglong2 a23 = Ap[k * 4 + 1];
                fma2(A0, w.x, a01.x); fma2(A1, w.y, a01.x);
                fma2(A2, w.x, a01.y); fma2(A3, w.y, a01.y);
                fma2(A4, w.x, a23.x); fma2(A5, w.y, a23.x);
                fma2(A6, w.x, a23.y); fma2(A7, w.y, a23.y);
            }
            float* P = part + (seg * 400 + cg * 4) * 8 + rh * 4;
            float2 v;
            v = up2(A0); P[0 * 8 + 0] = v.x; P[1 * 8 + 0] = v.y;
            v = up2(A1); P[2 * 8 + 0] = v.x; P[3 * 8 + 0] = v.y;
            v = up2(A2); P[0 * 8 + 1] = v.x; P[1 * 8 + 1] = v.y;
            v = up2(A3); P[2 * 8 + 1] = v.x; P[3 * 8 + 1] = v.y;
            v = up2(A4); P[0 * 8 + 2] = v.x; P[1 * 8 + 2] = v.y;
            v = up2(A5); P[2 * 8 + 2] = v.x; P[3 * 8 + 2] = v.y;
            v = up2(A6); P[0 * 8 + 3] = v.x; P[1 * 8 + 3] = v.y;
            v = up2(A7); P[2 * 8 + 3] = v.x; P[3 * 8 + 3] = v.y;
        }
        __syncthreads();

        // ---- combine3: reduce + bias/pre_obs + elu -> hho_dup ----
        if (tid < 400) {
            const int c = tid;
            if (c < 200) {
                const float b = bimg[c];
#pragma unroll
                for (int r = 0; r < 8; r++) {
                    float v = b + part[c * 8 + r] + part[(400 + c) * 8 + r];
                    hho_dup[c * 8 + r] = dup2(eluf(v));
                }
            } else {
                const int jj = c - 200;
                const float* po = g_pre_obs + ((size_t)t * Bc + b0) * Hc + jj;
#pragma unroll
                for (int r = 0; r < 8; r++) {
                    float v = po[r * Hc] + part[c * 8 + r] + part[(400 + c) * 8 + r];
                    hho_dup[c * 8 + r] = dup2(eluf(v));
                }
            }
        }
        __syncthreads();

        // ---- phase 4: stats preacts [200 x 120], k-split 4 ----
        if (tid < 240) {
            const int cg = tid % 30;
            const int z = tid / 30;            // 0..7
            const int rh = z & 1, seg = z >> 1;  // seg 0..3
            const bool post = cg >= 15;
            const int ci = post ? cg - 15 : cg;
            const float* W = (post ? w_obst : w_ims) + (size_t)seg * 50 * 60 + ci * 4;
            const ulonglong2* Wp = reinterpret_cast<const ulonglong2*>(W);
            const ulonglong2* Ap = reinterpret_cast<const ulonglong2*>(
                                       hho_dup + (post ? 200 * 8 : 0)) +
                                   (seg * 50) * 4 + rh * 2;
            ull A0 = 0, A1 = 0, A2 = 0, A3 = 0, A4 = 0, A5 = 0, A6 = 0, A7 = 0;
#pragma unroll 4
            for (int k = 0; k < 50; k++) {
                ulonglong2 w = Wp[(size_t)k * 15];
                ulonglong2 a01 = Ap[k * 4];
                ulonglong2 a23 = Ap[k * 4 + 1];
                fma2(A0, w.x, a01.x); fma2(A1, w.y, a01.x);
                fma2(A2, w.x, a01.y); fma2(A3, w.y, a01.y);
                fma2(A4, w.x, a23.x); fma2(A5, w.y, a23.x);
                fma2(A6, w.x, a23.y); fma2(A7, w.y, a23.y);
            }
            const int col = (post ? 60 : 0) + ci * 4;
            float* P = part + (seg * 120 + col) * 8 + rh * 4;
            float2 v;
            v = up2(A0); P[0 * 8 + 0] = v.x; P[1 * 8 + 0] = v.y;
            v = up2(A1); P[2 * 8 + 0] = v.x; P[3 * 8 + 0] = v.y;
            v = up2(A2); P[0 * 8 + 1] = v.x; P[1 * 8 + 1] = v.y;
            v = up2(A3); P[2 * 8 + 1] = v.x; P[3 * 8 + 1] = v.y;
            v = up2(A4); P[0 * 8 + 2] = v.x; P[1 * 8 + 2] = v.y;
            v = up2(A5); P[2 * 8 + 2] = v.x; P[3 * 8 + 2] = v.y;
            v = up2(A6); P[0 * 8 + 3] = v.x; P[1 * 8 + 3] = v.y;
            v = up2(A7); P[2 * 8 + 3] = v.x; P[3 * 8 + 3] = v.y;
        }
        __syncthreads();

        // ---- combine4: reduce 4 segs -> stS/soS ----
        if (tid < 120) {
            const int c = tid;
            const bool post = c >= 60;
            const int col = post ? c - 60 : c;
            const float b = post ? bobs[col] : bims[col];
            float* dst = post ? soS : stS;
#pragma unroll
            for (int r = 0; r < 8; r++) {
                float v = b + part[c * 8 + r] + part[(120 + c) * 8 + r] +
                          part[(240 + c) * 8 + r] + part[(360 + c) * 8 + r];
                dst[r * 64 + col] = v;
            }
        }
        __syncthreads();

        // ---- phase 5: sample, outputs, carry ----
        if (tid < 240) {
            const int r = tid / 30, k = tid - r * 30;
            const int b = b0 + r;
            float om  = soS[r * 64 + k];
            float osv = softplusf(soS[r * 64 + 30 + k]) + 0.1f;
            float ost = fmaf(osv, noise_o[((size_t)t * Bc + b) * Sc + k], om);
            float pm  = stS[r * 64 + k];
            float psv = softplusf(stS[r * 64 + 30 + k]) + 0.1f;
            float pst = fmaf(psv, noise_p[((size_t)t * Bc + b) * Sc + k], pm);
            size_t base = ((size_t)b * Tc + t) * OUTC;
            out[base + k]       = om;
            out[base + 30 + k]  = osv;
            out[base + 60 + k]  = ost;
            out[base + 90 + k]  = pm;
            out[base + 120 + k] = psv;
            out[base + 150 + k] = pst;
            st_f[k * 8 + r] = ost;
        }
        for (int i = tid; i < 1600; i += 640) {
            const int j = i % 200, r = i / 200;
            const float dnv = dn_fd[(j * 8 + r) * 2];
            out[((size_t)(b0 + r) * Tc + t) * OUTC + 180 + j] = dnv;
            xd_dup[(200 + j) * 8 + r] = dup2(dnv);
        }
        __syncthreads();
    }
}

// ===========================================================================
extern "C" void kernel_launch(void* const* d_in, const int* in_sizes, int n_in,
                              void* d_out, int out_size) {
    const float* embed       = (const float*)d_in[0];
    const float* action      = (const float*)d_in[1];
    const float* context     = (const float*)d_in[2];
    const float* noise_prior = (const float*)d_in[3];
    const float* noise_post  = (const float*)d_in[4];
    const float* w_inp       = (const float*)d_in[5];
    const float* b_inp       = (const float*)d_in[6];
    const float* w_gru       = (const float*)d_in[7];
    const float* b_gru       = (const float*)d_in[8];
    const float* w_img_out   = (const float*)d_in[9];
    const float* b_img_out   = (const float*)d_in[10];
    const float* w_obs_out   = (const float*)d_in[11];
    const float* b_obs_out   = (const float*)d_in[12];
    const float* w_ims_stat  = (const float*)d_in[13];
    const float* b_ims_stat  = (const float*)d_in[14];
    const float* w_obs_stat  = (const float*)d_in[15];
    const float* b_obs_stat  = (const float*)d_in[16];
    float* out = (float*)d_out;

    static int smem_set = 0;
    if (!smem_set) {
        cudaFuncSetAttribute(k_rssm, cudaFuncAttributeMaxDynamicSharedMemorySize,
                             SMEM_BYTES);
        smem_set = 1;
    }

    k_pre_inp<<<dim3(Bc * Tc / 64, 4), 128>>>(context, action, w_inp, b_inp);
    k_pre_obs<<<dim3(Bc * Tc / 64, 4), 128>>>(embed, w_obs_out, b_obs_out);
    k_rssm<<<NCTA, 640, SMEM_BYTES>>>(noise_prior, noise_post, w_inp, w_gru,
                                      b_gru, w_img_out, b_img_out, w_obs_out,
                                      w_ims_stat, b_ims_stat, w_obs_stat,
                                      b_obs_stat, out);
}

// round 6
// speedup vs baseline: 1.3034x; 1.3034x over previous
#include <cuda_runtime.h>
#include <cstdint>

// ---------------------------------------------------------------------------
// RSSM observe scan, GB300 — round 6.
//   k_rssm v4: 128 CTAs as 64 clusters of 2; cluster owns 8 batch rows;
//   each CTA computes half the output columns of every matmul (weights
//   column-sharded -> per-SM work halves, all 148 SMs busy). Cross-CTA
//   results exchanged via st.shared::cluster + barrier.cluster (3/step).
//   Pre-kernels reverted to the R3 (fastest measured) variant.
// ---------------------------------------------------------------------------

#define Bc 512
#define Tc 64
#define Ec 1024
#define Ac 32
#define Sc 30
#define Dc 200
#define Hc 200
#define SSc 230
#define OUTC 380

typedef unsigned long long ull;

__device__ float g_pre_inp[Tc * Bc * Hc];
__device__ float g_pre_obs[Tc * Bc * Hc];

// ---- packed f32x2 helpers -------------------------------------------------
__device__ __forceinline__ ull pk2(float a, float b) {
    ull r; asm("mov.b64 %0, {%1, %2};" : "=l"(r) : "f"(a), "f"(b)); return r;
}
__device__ __forceinline__ ull dup2(float a) {
    ull r; asm("mov.b64 %0, {%1, %1};" : "=l"(r) : "f"(a)); return r;
}
__device__ __forceinline__ float2 up2(ull v) {
    float x, y; asm("mov.b64 {%0, %1}, %2;" : "=f"(x), "=f"(y) : "l"(v));
    return make_float2(x, y);
}
__device__ __forceinline__ void fma2(ull& acc, ull a, ull b) {
    asm("fma.rn.f32x2 %0, %1, %2, %0;" : "+l"(acc) : "l"(a), "l"(b));
}

__device__ __forceinline__ float sigm(float x) { return 1.0f / (1.0f + __expf(-x)); }
__device__ __forceinline__ float eluf(float x) { return x > 0.0f ? x : expm1f(x); }
__device__ __forceinline__ float softplusf(float x) {
    return x > 15.0f ? x : log1pf(__expf(x));
}

// ---- cluster helpers --------------------------------------------------------
__device__ __forceinline__ uint32_t smem_u32(const void* p) {
    uint32_t a;
    asm("{ .reg .u64 t; cvta.to.shared.u64 t, %1; cvt.u32.u64 %0, t; }"
        : "=r"(a) : "l"(p));
    return a;
}
__device__ __forceinline__ void st_peer_u64(uint32_t laddr, uint32_t rank, ull v) {
    uint32_t ra;
    asm volatile("mapa.shared::cluster.u32 %0, %1, %2;" : "=r"(ra)
                 : "r"(laddr), "r"(rank));
    asm volatile("st.shared::cluster.u64 [%0], %1;" :: "r"(ra), "l"(v) : "memory");
}
__device__ __forceinline__ void st_peer_f32(uint32_t laddr, uint32_t rank, float v) {
    uint32_t ra;
    asm volatile("mapa.shared::cluster.u32 %0, %1, %2;" : "=r"(ra)
                 : "r"(laddr), "r"(rank));
    asm volatile("st.shared::cluster.f32 [%0], %1;" :: "r"(ra), "f"(v) : "memory");
}
__device__ __forceinline__ uint32_t ctarank() {
    uint32_t r; asm("mov.u32 %0, %%cluster_ctarank;" : "=r"(r)); return r;
}
#define CB() do { asm volatile("barrier.cluster.arrive.aligned;" ::: "memory"); \
                  asm volatile("barrier.cluster.wait.aligned;" ::: "memory"); } while (0)

// ===========================================================================
// k_pre_obs / k_pre_inp: R3 variants (fastest measured)
// ===========================================================================
__global__ void __launch_bounds__(128) k_pre_obs(const float* __restrict__ embed,
                                                 const float* __restrict__ w_obs,
                                                 const float* __restrict__ b_obs) {
    __shared__ __align__(8) float As[16][66];
    const int tid = threadIdx.x;
    const int jp = tid & 31, rg = tid >> 5;
    const int row0 = blockIdx.x * 64;
    const int j0 = blockIdx.y * 64 + jp * 2;
    const bool act = (j0 < Hc);
    const int rbase = rg * 16;

    ull acc[16];
#pragma unroll
    for (int i = 0; i < 16; i++) acc[i] = 0ull;

    for (int k0 = 0; k0 < Ec; k0 += 16) {
#pragma unroll
        for (int i = 0; i < 8; i++) {
            int lin = tid + i * 128;
            int kk = lin & 15, r = lin >> 4;
            int rowg = row0 + r;
            int tt = rowg >> 9, bb = rowg & 511;
            As[kk][r] = embed[(size_t)(bb * Tc + tt) * Ec + k0 + kk];
        }
        __syncthreads();
        if (act) {
#pragma unroll
            for (int kk = 0; kk < 16; kk++) {
                float2 w = *reinterpret_cast<const float2*>(
                    w_obs + (size_t)(Dc + k0 + kk) * Hc + j0);
                ull wx = dup2(w.x), wy = dup2(w.y);
                const ull* ap = reinterpret_cast<const ull*>(&As[kk][rbase]);
#pragma unroll
                for (int pq = 0; pq < 8; pq++) {
                    ull a = ap[pq];
                    fma2(acc[2 * pq], a, wx);
                    fma2(acc[2 * pq + 1], a, wy);
                }
            }
        }
        __syncthreads();
    }
    if (act) {
        float bx = b_obs[j0], by = b_obs[j0 + 1];
#pragma unroll
        for (int pq = 0; pq < 8; pq++) {
            float2 va = up2(acc[2 * pq]), vb = up2(acc[2 * pq + 1]);
            int r = row0 + rbase + 2 * pq;
            *reinterpret_cast<float2*>(g_pre_obs + (size_t)r * Hc + j0) =
                make_float2(va.x + bx, vb.x + by);
            *reinterpret_cast<float2*>(g_pre_obs + (size_t)(r + 1) * Hc + j0) =
                make_float2(va.y + bx, vb.y + by);
        }
    }
}

__global__ void __launch_bounds__(128) k_pre_inp(const float* __restrict__ ctx,
                                                 const float* __restrict__ actn,
                                                 const float* __restrict__ w_inp,
                                                 const float* __restrict__ b_inp) {
    __shared__ __align__(8) float As[16][66];
    const int tid = threadIdx.x;
    const int jp = tid & 31, rg = tid >> 5;
    const int row0 = blockIdx.x * 64;
    const int j0 = blockIdx.y * 64 + jp * 2;
    const bool act = (j0 < Hc);
    const int rbase = rg * 16;

    ull acc[16];
#pragma unroll
    for (int i = 0; i < 16; i++) acc[i] = 0ull;

    for (int k0 = 0; k0 < 272; k0 += 16) {
#pragma unroll
        for (int i = 0; i < 8; i++) {
            int lin = tid + i * 128;
            int kk = lin & 15, r = lin >> 4;
            int rowg = row0 + r;
            int tt = rowg >> 9, bb = rowg & 511;
            int k = k0 + kk;
            float v = 0.0f;
            if (k < SSc)            v = ctx[(size_t)(bb * Tc + tt) * SSc + k];
            else if (k < SSc + Ac)  v = actn[(size_t)(bb * Tc + tt) * Ac + (k - SSc)];
            As[kk][r] = v;
        }
        __syncthreads();
        if (act) {
#pragma unroll
            for (int kk = 0; kk < 16; kk++) {
                int kw = (k0 + kk < SSc + Ac) ? (k0 + kk) : (SSc + Ac - 1);
                float2 w = *reinterpret_cast<const float2*>(
                    w_inp + (size_t)(Sc + kw) * Hc + j0);
                ull wx = dup2(w.x), wy = dup2(w.y);
                const ull* ap = reinterpret_cast<const ull*>(&As[kk][rbase]);
#pragma unroll
                for (int pq = 0; pq < 8; pq++) {
                    ull a = ap[pq];
                    fma2(acc[2 * pq], a, wx);
                    fma2(acc[2 * pq + 1], a, wy);
                }
            }
        }
        __syncthreads();
    }
    if (act) {
        float bx = b_inp[j0], by = b_inp[j0 + 1];
#pragma unroll
        for (int pq = 0; pq < 8; pq++) {
            float2 va = up2(acc[2 * pq]), vb = up2(acc[2 * pq + 1]);
            int r = row0 + rbase + 2 * pq;
            *reinterpret_cast<float2*>(g_pre_inp + (size_t)r * Hc + j0) =
                make_float2(va.x + bx, vb.x + by);
            *reinterpret_cast<float2*>(g_pre_inp + (size_t)(r + 1) * Hc + j0) =
                make_float2(va.y + bx, vb.y + by);
        }
    }
}

// ===========================================================================
// k_rssm v4 — smem layout (bytes):
//  XD   [400][8] ull  @      0  (25600)  x||d duplicated values (a,a)
//  DN   [200][8] ull  @  25600  (12800)  deter_new dup (full in both CTAs)
//  HHO  [400][8] ull  @  38400  (25600)  h||ho dup (full in both CTAs)
//  PART 5100 ull      @  64000  (40800)  k-split partials, 17-ull group stride
//  STS  [8][64] f32   @ 104800  ( 2048)
//  SOS  [8][64] f32   @ 106848  ( 2048)
//  STF  [32][8] f32   @ 108896  ( 1024)  stoch carry
//  BGRU 600 f32       @ 109920  ( 2400)
//  BIMG 200 f32       @ 112320  (  800)
//  BIMS 64 f32        @ 113120  (  256)
//  BOBS 64 f32        @ 113376  (  256)   total 113632
// ===========================================================================
#define XD_OFF   0
#define DN_OFF   25600
#define HHO_OFF  38400
#define PART_OFF 64000
#define STS_OFF  104800
#define SOS_OFF  106848
#define STF_OFF  108896
#define BGRU_OFF 109920
#define BIMG_OFF 112320
#define BIMS_OFF 113120
#define BOBS_OFF 113376
#define SMEM_BYTES 113632

__global__ void __launch_bounds__(640, 1) __cluster_dims__(2, 1, 1) k_rssm(
    const float* __restrict__ noise_p, const float* __restrict__ noise_o,
    const float* __restrict__ w_inp,  const float* __restrict__ w_gru,
    const float* __restrict__ b_gru_g,
    const float* __restrict__ w_img,  const float* __restrict__ b_img_g,
    const float* __restrict__ w_obsd,
    const float* __restrict__ w_ims,  const float* __restrict__ b_ims_g,
    const float* __restrict__ w_obst, const float* __restrict__ b_obst_g,
    float* __restrict__ out) {
    extern __shared__ __align__(16) char sm[];
    ull*   xd_u   = reinterpret_cast<ull*>(sm + XD_OFF);
    ull*   dn_u   = reinterpret_cast<ull*>(sm + DN_OFF);
    ull*   hho_u  = reinterpret_cast<ull*>(sm + HHO_OFF);
    ull*   part_u = reinterpret_cast<ull*>(sm + PART_OFF);
    float* part_f = reinterpret_cast<float*>(sm + PART_OFF);
    float* stS    = reinterpret_cast<float*>(sm + STS_OFF);
    float* soS    = reinterpret_cast<float*>(sm + SOS_OFF);
    float* st_f   = reinterpret_cast<float*>(sm + STF_OFF);
    float* bgru   = reinterpret_cast<float*>(sm + BGRU_OFF);
    float* bimg   = reinterpret_cast<float*>(sm + BIMG_OFF);
    float* bims   = reinterpret_cast<float*>(sm + BIMS_OFF);
    float* bobs   = reinterpret_cast<float*>(sm + BOBS_OFF);
    const ulonglong2* xd_u2 = reinterpret_cast<const ulonglong2*>(xd_u);
    const ulonglong2* dn_u2 = reinterpret_cast<const ulonglong2*>(dn_u);
    const ulonglong2* hho_u2 = reinterpret_cast<const ulonglong2*>(hho_u);
    const float* xd_f = reinterpret_cast<const float*>(xd_u);
    const float* dn_f = reinterpret_cast<const float*>(dn_u);

    const int tid = threadIdx.x;
    const uint32_t p = ctarank();          // 0 or 1
    const uint32_t peer = 1u - p;
    const int b0 = (blockIdx.x >> 1) * 8;  // 8 rows per cluster
    const uint32_t base32 = smem_u32(sm);

    for (int i = tid; i < 600; i += 640) bgru[i] = b_gru_g[i];
    for (int i = tid; i < Hc; i += 640) bimg[i] = b_img_g[i];
    if (tid < 60) { bims[tid] = b_ims_g[tid]; bobs[tid] = b_obst_g[tid]; }
    for (int i = tid; i < 1600; i += 640) xd_u[1600 + i] = 0ull;   // d = 0
    for (int i = tid; i < 256; i += 640) st_f[i] = 0.0f;           // stoch = 0
    __syncthreads();
    CB();

    for (int t = 0; t < Tc; t++) {
        // ---- phase 1: x = elu(stoch @ Wis + pre_inp[t]) — full, duplicated ----
        if (tid < 400) {
            const int j = tid >> 1, rh = tid & 1;
            const float* pi = g_pre_inp + ((size_t)t * Bc + b0) * Hc + j;
            float a0 = pi[(rh * 4 + 0) * Hc], a1 = pi[(rh * 4 + 1) * Hc];
            float a2 = pi[(rh * 4 + 2) * Hc], a3 = pi[(rh * 4 + 3) * Hc];
#pragma unroll
            for (int k = 0; k < Sc; k++) {
                float w = w_inp[k * Hc + j];
                float4 s = *reinterpret_cast<const float4*>(&st_f[k * 8 + rh * 4]);
                a0 = fmaf(w, s.x, a0); a1 = fmaf(w, s.y, a1);
                a2 = fmaf(w, s.z, a2); a3 = fmaf(w, s.w, a3);
            }
            ull* xo = &xd_u[j * 8 + rh * 4];
            xo[0] = dup2(eluf(a0)); xo[1] = dup2(eluf(a1));
            xo[2] = dup2(eluf(a2)); xo[3] = dup2(eluf(a3));
        }
        __syncthreads();

        // ---- phase 2: GRU preacts, our 300 of 600 gate-cols; k-split 4 ----
        if (tid < 600) {
            const int cg = tid % 75;
            const int z = tid / 75;
            const int rh = z & 1, seg = z >> 1;
            const int lc0 = cg * 4;
            const int gcol0 = (lc0 / 100) * 200 + (int)p * 100 + (lc0 % 100);
            const ulonglong2* Wp = reinterpret_cast<const ulonglong2*>(w_gru + gcol0)
                                   + (size_t)seg * 100 * 150;
            const ulonglong2* Ap = xd_u2 + (seg * 100) * 4 + rh * 2;
            ull A0 = 0, A1 = 0, A2 = 0, A3 = 0, A4 = 0, A5 = 0, A6 = 0, A7 = 0;
#pragma unroll 5
            for (int kk = 0; kk < 100; kk++) {
                ulonglong2 w = Wp[(size_t)kk * 150];
                ulonglong2 a01 = Ap[kk * 4];
                ulonglong2 a23 = Ap[kk * 4 + 1];
                fma2(A0, w.x, a01.x); fma2(A1, w.y, a01.x);
                fma2(A2, w.x, a01.y); fma2(A3, w.y, a01.y);
                fma2(A4, w.x, a23.x); fma2(A5, w.y, a23.x);
                fma2(A6, w.x, a23.y); fma2(A7, w.y, a23.y);
            }
            ull* P = part_u + (seg * 75 + cg) * 17 + rh * 4;
            P[0] = A0; P[8] = A1; P[1] = A2; P[9] = A3;
            P[2] = A4; P[10] = A5; P[3] = A6; P[11] = A7;
        }
        __syncthreads();

        // ---- combine2: gates -> deter_new (our 100 cols), dup to both CTAs ----
        if (tid < 400) {
            const int j = tid >> 2, q = tid & 3;
            const int gd = (int)p * 100 + j;
            const int jq = j >> 2, ci = j & 3, cp = ci >> 1, e = ci & 1;
            const float bR = bgru[gd], bC = bgru[200 + gd], bU = bgru[400 + gd];
#pragma unroll
            for (int w2 = 0; w2 < 2; w2++) {
                const int rr = q * 2 + w2;
                float R = bR, C = bC, U = bU - 1.0f;
#pragma unroll
                for (int seg = 0; seg < 4; seg++) {
                    R += part_f[(((seg * 75 + 0 * 25 + jq) * 17 + cp * 8 + rr) << 1) + e];
                    C += part_f[(((seg * 75 + 1 * 25 + jq) * 17 + cp * 8 + rr) << 1) + e];
                    U += part_f[(((seg * 75 + 2 * 25 + jq) * 17 + cp * 8 + rr) << 1) + e];
                }
                float reset = sigm(R);
                float cand  = tanhf(reset * C);
                float upd   = sigm(U);
                float dprev = xd_f[((200 + gd) * 8 + rr) * 2];
                float dnv = upd * cand + (1.0f - upd) * dprev;
                ull dv = dup2(dnv);
                dn_u[gd * 8 + rr] = dv;
                st_peer_u64(base32 + DN_OFF + (uint32_t)(gd * 8 + rr) * 8, peer, dv);
            }
        }
        CB();   // dn full everywhere

        // ---- phase 3: h/ho (our 100+100 cols), k-split 4 ∥ deter out + carry ----
        if (tid < 400) {
            const int grp = tid % 50;
            const int z = tid / 50;
            const int rh = z & 1, seg = z >> 1;
            const float* W = (grp < 25)
                ? (w_img + (int)p * 100 + grp * 4)
                : (w_obsd + (int)p * 100 + (grp - 25) * 4);
            const ulonglong2* Wp = reinterpret_cast<const ulonglong2*>(W)
                                   + (size_t)(seg * 50) * 50;
            const ulonglong2* Ap = dn_u2 + (seg * 50) * 4 + rh * 2;
            ull A0 = 0, A1 = 0, A2 = 0, A3 = 0, A4 = 0, A5 = 0, A6 = 0, A7 = 0;
#pragma unroll 5
            for (int kk = 0; kk < 50; kk++) {
                ulonglong2 w = Wp[(size_t)kk * 50];
                ulonglong2 a01 = Ap[kk * 4];
                ulonglong2 a23 = Ap[kk * 4 + 1];
                fma2(A0, w.x, a01.x); fma2(A1, w.y, a01.x);
                fma2(A2, w.x, a01.y); fma2(A3, w.y, a01.y);
                fma2(A4, w.x, a23.x); fma2(A5, w.y, a23.x);
                fma2(A6, w.x, a23.y); fma2(A7, w.y, a23.y);
            }
            ull* P = part_u + (seg * 50 + grp) * 17 + rh * 4;
            P[0] = A0; P[8] = A1; P[1] = A2; P[9] = A3;
            P[2] = A4; P[10] = A5; P[3] = A6; P[11] = A7;
        } else {
            const int tt2 = tid - 400;
            // deter gmem: our 4 rows
            for (int i = tt2; i < 800; i += 240) {
                const int rl = i / 200, j = i % 200;
                const int r = (int)p * 4 + rl;
                out[((size_t)(b0 + r) * Tc + t) * OUTC + 180 + j] =
                    dn_f[(j * 8 + r) * 2];
            }
            // carry: xd d-part <- deter_new (full, local copy)
            for (int i = tt2; i < 1600; i += 240) xd_u[1600 + i] = dn_u[i];
        }
        __syncthreads();

        // ---- combine3: + bias / pre_obs, elu -> hho dup to both CTAs ----
        if (tid < 400) {
            const int cl = tid >> 1;            // 0..199 local col
            const int rh = (tid & 1) * 4;
            const bool ish = cl < 100;
            const int gcol = (int)p * 100 + (ish ? cl : cl - 100);
            const int grp = ish ? (cl >> 2) : (25 + ((cl - 100) >> 2));
            const int ci = cl & 3, cp = ci >> 1, e = ci & 1;
            const float* po = g_pre_obs + ((size_t)t * Bc + b0) * Hc + gcol;
            const float bb = ish ? bimg[gcol] : 0.0f;
            const int dsti = ish ? gcol : 200 + gcol;
#pragma unroll
            for (int i = 0; i < 4; i++) {
                const int r = rh + i;
                float v = ish ? bb : po[r * Hc];
#pragma unroll
                for (int seg = 0; seg < 4; seg++)
                    v += part_f[(((seg * 50 + grp) * 17 + cp * 8 + r) << 1) + e];
                ull dv = dup2(eluf(v));
                hho_u[dsti * 8 + r] = dv;
                st_peer_u64(base32 + HHO_OFF + (uint32_t)(dsti * 8 + r) * 8, peer, dv);
            }
        }
        CB();   // hho full everywhere

        // ---- phase 4: stats. CTA0: stS=h@Wims; CTA1: soS=ho@Wobst. k-split 8 ----
        if (tid < 240) {
            const int grp = tid % 15;
            const int z = tid / 15;                // 0..15
            const int rh = z & 1, seg = z >> 1;    // seg 0..7, K=25
            const float* W = (p ? w_obst : w_ims) + grp * 4;
            const ulonglong2* Wp = reinterpret_cast<const ulonglong2*>(W)
                                   + (size_t)(seg * 25) * 15;
            const ulonglong2* Ap = hho_u2 + (int)p * 800 + (seg * 25) * 4 + rh * 2;
            ull A0 = 0, A1 = 0, A2 = 0, A3 = 0, A4 = 0, A5 = 0, A6 = 0, A7 = 0;
#pragma unroll 5
            for (int kk = 0; kk < 25; kk++) {
                ulonglong2 w = Wp[(size_t)kk * 15];
                ulonglong2 a01 = Ap[kk * 4];
                ulonglong2 a23 = Ap[kk * 4 + 1];
                fma2(A0, w.x, a01.x); fma2(A1, w.y, a01.x);
                fma2(A2, w.x, a01.y); fma2(A3, w.y, a01.y);
                fma2(A4, w.x, a23.x); fma2(A5, w.y, a23.x);
                fma2(A6, w.x, a23.y); fma2(A7, w.y, a23.y);
            }
            ull* P = part_u + (seg * 15 + grp) * 17 + rh * 4;
            P[0] = A0; P[8] = A1; P[1] = A2; P[9] = A3;
            P[2] = A4; P[10] = A5; P[3] = A6; P[11] = A7;
        }
        __syncthreads();

        // ---- combine4: reduce 8 segs + bias -> stat array, dup to peer ----
        if (tid < 240) {
            const int col = tid >> 2, q = tid & 3;
            const int cgq = col >> 2, ci = col & 3, cp = ci >> 1, e = ci & 1;
            const float bb = p ? bobs[col] : bims[col];
            const uint32_t dstoff = p ? SOS_OFF : STS_OFF;
            float* dst = reinterpret_cast<float*>(sm + dstoff);
#pragma unroll
            for (int w2 = 0; w2 < 2; w2++) {
                const int rr = q * 2 + w2;
                float v = bb;
#pragma unroll
                for (int seg = 0; seg < 8; seg++)
                    v += part_f[(((seg * 15 + cgq) * 17 + cp * 8 + rr) << 1) + e];
                dst[rr * 64 + col] = v;
                st_peer_f32(base32 + dstoff + (uint32_t)(rr * 64 + col) * 4, peer, v);
            }
        }
        CB();   // stS/soS full everywhere

        // ---- phase 5: sample (both CTAs, carry), gmem stats (split rows) ----
        if (tid < 240) {
            const int r = tid / 30, k = tid - r * 30;
            const int b = b0 + r;
            float om  = soS[r * 64 + k];
            float osv = softplusf(soS[r * 64 + 30 + k]) + 0.1f;
            float ost = fmaf(osv, noise_o[((size_t)t * Bc + b) * Sc + k], om);
            st_f[k * 8 + r] = ost;
            if ((r >> 2) == (int)p) {
                float pm  = stS[r * 64 + k];
                float psv = softplusf(stS[r * 64 + 30 + k]) + 0.1f;
                float pst = fmaf(psv, noise_p[((size_t)t * Bc + b) * Sc + k], pm);
                size_t basep = ((size_t)b * Tc + t) * OUTC;
                out[basep + k]       = om;
                out[basep + 30 + k]  = osv;
                out[basep + 60 + k]  = ost;
                out[basep + 90 + k]  = pm;
                out[basep + 120 + k] = psv;
                out[basep + 150 + k] = pst;
            }
        }
        __syncthreads();
    }
}

// ===========================================================================
extern "C" void kernel_launch(void* const* d_in, const int* in_sizes, int n_in,
                              void* d_out, int out_size) {
    const float* embed       = (const float*)d_in[0];
    const float* action      = (const float*)d_in[1];
    const float* context     = (const float*)d_in[2];
    const float* noise_prior = (const float*)d_in[3];
    const float* noise_post  = (const float*)d_in[4];
    const float* w_inp       = (const float*)d_in[5];
    const float* b_inp       = (const float*)d_in[6];
    const float* w_gru       = (const float*)d_in[7];
    const float* b_gru       = (const float*)d_in[8];
    const float* w_img_out   = (const float*)d_in[9];
    const float* b_img_out   = (const float*)d_in[10];
    const float* w_obs_out   = (const float*)d_in[11];
    const float* b_obs_out   = (const float*)d_in[12];
    const float* w_ims_stat  = (const float*)d_in[13];
    const float* b_ims_stat  = (const float*)d_in[14];
    const float* w_obs_stat  = (const float*)d_in[15];
    const float* b_obs_stat  = (const float*)d_in[16];
    float* out = (float*)d_out;

    static int smem_set = 0;
    if (!smem_set) {
        cudaFuncSetAttribute(k_rssm, cudaFuncAttributeMaxDynamicSharedMemorySize,
                             SMEM_BYTES);
        smem_set = 1;
    }

    k_pre_inp<<<dim3(Bc * Tc / 64, 4), 128>>>(context, action, w_inp, b_inp);
    k_pre_obs<<<dim3(Bc * Tc / 64, 4), 128>>>(embed, w_obs_out, b_obs_out);
    k_rssm<<<128, 640, SMEM_BYTES>>>(noise_prior, noise_post, w_inp, w_gru,
                                     b_gru, w_img_out, b_img_out, w_obs_out,
                                     w_ims_stat, b_ims_stat, w_obs_stat,
                                     b_obs_stat, out);
}